// round 15
// baseline (speedup 1.0000x reference)
#include <cuda_runtime.h>
#include <stdint.h>

// HierarchicalRingTopK: 3x3x3 VALID conv (120 ch) + 4-level gated top-k keep.
// x: (8,3,256,256) f32, w: (120,3,3,3) f32, b: (120,) f32 -> out: (8,120,254,254) f32
//
// FROZEN NUMERICS (rel_err == 0.0 since R4): per-channel serial fp32 FMA chain
// over the 27 taps in NHWC patch order (kh, kw, c innermost) from 0, bias
// added as a separate fp32 add. Top-k: magnitude strict-> scan, lower index
// wins ties. f32x2 lanes are independent rn-FMAs (bit-identical).
//
// R14 = R11 base plus:
//  - Levels 0-2 weights served from __constant__ memory (separate HW port from
//    L1tex): padded 28f/channel layout -> 7 LDC.128 per channel; conv as two
//    interleaved scalar FFMA chains per pair (per-lane identical numerics).
//    Removes 392 of 840 weight LDS wavefronts from the saturated L1 pipe.
//  - Level 3 stays on smem + ffma2 (port balance: L1 ~985 vs const ~784).
//  - Keys stored as raw float bits (mag = bits & 0x7FFFFFFF, decode free).

#define BT 160
#define OH 254
#define OW 254
#define PLANE (OH * OW)          // 64516
#define NPIX (8 * PLANE)         // 516128
#define NCH 120
#define NPAIR3 32                // level-3 channel pairs (channels 56..119)
#define ENC_BYTES (64 * BT * 4)  // 40960 (dynamic smem)

__constant__ float cw28[NCH * 28];   // padded weights: cw28[c*28 + q], q<27
__constant__ float cbias[NCH];

__device__ __forceinline__ unsigned long long ffma2(unsigned long long a,
                                                    unsigned long long bb_,
                                                    unsigned long long c) {
    unsigned long long d;
    asm("fma.rn.f32x2 %0, %1, %2, %3;" : "=l"(d) : "l"(a), "l"(bb_), "l"(c));
    return d;
}
__device__ __forceinline__ unsigned long long pack2(float lo, float hi) {
    unsigned long long r;
    asm("mov.b64 %0, {%1, %2};" : "=l"(r) : "f"(lo), "f"(hi));
    return r;
}
__device__ __forceinline__ void unpack2(unsigned long long v, float& lo, float& hi) {
    asm("mov.b64 {%0, %1}, %2;" : "=f"(lo), "=f"(hi) : "l"(v));
}
__device__ __forceinline__ float lo2(unsigned long long v) {
    float a, b2;
    unpack2(v, a, b2);
    return a;          // register alias of the low half (no data movement)
}

// Gating: selected j -> enable bits 2j..2j+3 (mod 2n). Branch-free bit-spread.
// Validated rel_err==0.0 in R8-R13. Handles the j==31 wrap for n=32.
__device__ __forceinline__ unsigned long long gate_from_sel(unsigned m, int n) {
    unsigned long long xv = m;
    xv = (xv | (xv << 16)) & 0x0000FFFF0000FFFFull;
    xv = (xv | (xv << 8 )) & 0x00FF00FF00FF00FFull;
    xv = (xv | (xv << 4 )) & 0x0F0F0F0F0F0F0F0Full;
    xv = (xv | (xv << 2 )) & 0x3333333333333333ull;
    xv = (xv | (xv << 1 )) & 0x5555555555555555ull;     // bit j -> bit 2j
    unsigned long long gg = xv | (xv << 1) | (xv << 2) | (xv << 3);
    if (n == 32 && (m >> 31)) gg |= 0x3ull;             // wrap of j=31
    const int Wn = n * 2;
    if (Wn < 64)
        gg = (gg | (gg >> Wn)) & ((1ull << Wn) - 1ull);
    return gg;
}

__global__ void __launch_bounds__(BT, 4)
hrtk_kernel(const float* __restrict__ x,
            const float* __restrict__ w,
            const float* __restrict__ b,
            float* __restrict__ out)
{
    // Level-3-only pair-interleaved weights (pairs 28..59):
    // wsh2[lp*56 + 2q+e] = w[56 + 2lp + e][q]; +54/+55 = biases.
    __shared__ float wsh2[NPAIR3 * 56];              // 7168 B (static)
    extern __shared__ unsigned sEnc[];               // 64 key columns x BT (dynamic)

    const int t = threadIdx.x;

    for (int q = t; q < NPAIR3 * 56; q += BT) {
        const int lp = q / 56;
        const int r  = q - lp * 56;
        wsh2[q] = (r < 54) ? w[(56 + lp * 2 + (r & 1)) * 27 + (r >> 1)]
                           : b[56 + lp * 2 + (r - 54)];
    }
    __syncthreads();

    const int p = blockIdx.x * BT + t;
    if (p >= NPIX) return;
    // NPIX = 160*3225 + 128: tail block keeps warps 0-3 fully live, warp 4
    // exits whole -> full-mask shuffles safe in every surviving warp.

    const int ww = p % OW;
    const int rest = p / OW;
    const int hh = rest % OH;
    const int bb = rest / OH;

    unsigned long long win2[27];
    const float* xb = x + (size_t)bb * (3 * 65536) + hh * 256 + ww;
#pragma unroll
    for (int ci = 0; ci < 3; ci++)
#pragma unroll
        for (int kh = 0; kh < 3; kh++)
#pragma unroll
            for (int kw = 0; kw < 3; kw++) {
                const float v = __ldg(xb + ci * 65536 + kh * 256 + kw);
                win2[ci * 9 + kh * 3 + kw] = pack2(v, v);
            }

    float* ob = out + (size_t)bb * (NCH * PLANE) + hh * OW + ww;

    unsigned long long gate = ~0ull;
    int base = 0;

#pragma unroll
    for (int lvl = 0; lvl < 4; lvl++) {
        const int n = 8 << lvl;   // 8,16,32,64
        const int k = 2 << lvl;   // 2,4,8,16
        const int G = n >> 3;     // groups of 8 channels

        // Warp-union of gates (uniform liveness for dead-group skip).
        unsigned long long ugate = ~0ull;
        if (lvl > 0) {
            unsigned lo = (unsigned)gate, hi = (unsigned)(gate >> 32);
#pragma unroll
            for (int o = 16; o; o >>= 1) {
                lo |= __shfl_xor_sync(0xffffffffu, lo, o);
                hi |= __shfl_xor_sync(0xffffffffu, hi, o);
            }
            ugate = ((unsigned long long)hi << 32) | lo;
        }

        unsigned gmag[8];
#pragma unroll
        for (int g = 0; g < 8; g++) gmag[g] = 0u;

        // ---- conv + encode + zero-prefill + group-max build ----
#pragma unroll
        for (int g = 0; g < G; g++) {
            const int ib = g << 3;
            unsigned gm = 0u;
            if (((ugate >> ib) & 0xFFull) == 0ull) {
#pragma unroll
                for (int j = 0; j < 8; j++) {
                    sEnc[(ib + j) * BT + t] = 0u;
                    ob[(base + ib + j) * PLANE] = 0.0f;
                }
            } else {
#pragma unroll
                for (int j2 = 0; j2 < 4; j2++) {            // 4 channel-pairs
                    const int i0 = ib + j2 * 2;
                    float act0, act1;

                    if (lvl < 3) {
                        // Constant-port path: padded layout, 7 LDC.128/channel,
                        // two interleaved scalar chains (frozen per-lane order).
                        const int c0 = base + i0;
                        const float4* w0 = (const float4*)(cw28 + c0 * 28);
                        const float4* w1 = (const float4*)(cw28 + (c0 + 1) * 28);
                        float wr0[28], wr1[28];
#pragma unroll
                        for (int z = 0; z < 7; z++) {
                            *(float4*)&wr0[4 * z] = w0[z];
                            *(float4*)&wr1[4 * z] = w1[z];
                        }
                        float a0 = 0.0f, a1 = 0.0f;
#pragma unroll
                        for (int kh = 0; kh < 3; kh++)
#pragma unroll
                            for (int kw = 0; kw < 3; kw++)
#pragma unroll
                                for (int ci = 0; ci < 3; ci++) {
                                    const int q = ci * 9 + kh * 3 + kw;
                                    const float wv = lo2(win2[q]);
                                    a0 = fmaf(wv, wr0[q], a0);
                                    a1 = fmaf(wv, wr1[q], a1);
                                }
                        act0 = a0 + cbias[c0];
                        act1 = a1 + cbias[c0 + 1];
                    } else {
                        // Smem path (level 3): pair-interleaved ffma2 chain.
                        const int lp = (base + i0 - 56) >> 1;
                        const float4* wv = (const float4*)(wsh2 + lp * 56);
                        float wrp[56];
#pragma unroll
                        for (int z = 0; z < 14; z++) *(float4*)&wrp[4 * z] = wv[z];

                        unsigned long long acc = 0ull;
#pragma unroll
                        for (int kh = 0; kh < 3; kh++)
#pragma unroll
                            for (int kw = 0; kw < 3; kw++)
#pragma unroll
                                for (int ci = 0; ci < 3; ci++) {
                                    const int q = ci * 9 + kh * 3 + kw;
                                    acc = ffma2(win2[q],
                                                *(const unsigned long long*)&wrp[2 * q],
                                                acc);
                                }
                        float a0, a1;
                        unpack2(acc, a0, a1);
                        act0 = a0 + wrp[54];
                        act1 = a1 + wrp[55];
                    }

                    // Raw-bits keys: mag = bits & 0x7FFFFFFF, decode is identity.
                    unsigned k0 = __float_as_uint(act0);
                    unsigned k1 = __float_as_uint(act1);
                    k0 = ((unsigned)(gate >> (i0    )) & 1u) ? k0 : 0u;
                    k1 = ((unsigned)(gate >> (i0 + 1)) & 1u) ? k1 : 0u;
                    sEnc[(i0    ) * BT + t] = k0;
                    sEnc[(i0 + 1) * BT + t] = k1;
                    ob[(base + i0    ) * PLANE] = 0.0f;
                    ob[(base + i0 + 1) * PLANE] = 0.0f;
                    const unsigned um0 = k0 & 0x7FFFFFFFu;
                    const unsigned um1 = k1 & 0x7FFFFFFFu;
                    if (um0 > gm) gm = um0;                  // ascending order:
                    if (um1 > gm) gm = um1;                  // first-wins kept
                }
            }
            gmag[g] = gm;
        }

        // ---- k extractions: register group-max scan + one 8-slot rescan ----
        unsigned selmask = 0u;
#pragma unroll 1
        for (int s = 0; s < k; s++) {
            unsigned bm = 0u;
            int bg = 0;
#pragma unroll
            for (int g = 0; g < 8; g++)
                if (g < G && gmag[g] > bm) { bm = gmag[g]; bg = g; }  // strict >
            if (!bm) break;                       // all remaining keys are zero

            unsigned m2 = 0u, ufull = 0u, found = 0u;
            int leaf = 0;
            const int gb = bg << 3;
#pragma unroll
            for (int j = 0; j < 8; j++) {
                const unsigned u = sEnc[(gb + j) * BT + t];
                const unsigned um = u & 0x7FFFFFFFu;
                if (um == bm && !found) { found = 1u; leaf = j; ufull = u; }
                else if (um > m2) m2 = um;
            }
            const int mi = gb + leaf;
            ob[(base + mi) * PLANE] = __uint_as_float(ufull);
            sEnc[mi * BT + t] = 0u;
#pragma unroll
            for (int g = 0; g < 8; g++)
                if (g == bg) gmag[g] = m2;
            selmask |= 1u << mi;
        }

        if (lvl < 3)
            gate = gate_from_sel(selmask, n);
        base += n;
    }
}

extern "C" void kernel_launch(void* const* d_in, const int* in_sizes, int n_in,
                              void* d_out, int out_size)
{
    const float* x = (const float*)d_in[0];
    const float* w = (const float*)d_in[1];
    const float* b = (const float*)d_in[2];
    float* out = (float*)d_out;

    static void* cw_addr = nullptr;
    if (!cw_addr) {
        cudaFuncSetAttribute(hrtk_kernel,
                             cudaFuncAttributeMaxDynamicSharedMemorySize,
                             ENC_BYTES);
        cudaGetSymbolAddress(&cw_addr, cw28);
    }

    // Re-layout OIHW (27f/ch) -> padded (28f/ch) constant in one memcpy node.
    cudaMemcpy2DAsync(cw_addr, 28 * sizeof(float),
                      w, 27 * sizeof(float),
                      27 * sizeof(float), NCH,
                      cudaMemcpyDeviceToDevice);
    cudaMemcpyToSymbolAsync(cbias, b, NCH * sizeof(float), 0,
                            cudaMemcpyDeviceToDevice);

    const int grid = (NPIX + BT - 1) / BT;
    hrtk_kernel<<<grid, BT, ENC_BYTES>>>(x, w, b, out);
}

// round 16
// speedup vs baseline: 1.0511x; 1.0511x over previous
#include <cuda_runtime.h>
#include <stdint.h>

// HierarchicalRingTopK: 3x3x3 VALID conv (120 ch) + 4-level gated top-k keep.
// x: (8,3,256,256) f32, w: (120,3,3,3) f32, b: (120,) f32 -> out: (8,120,254,254) f32
//
// FROZEN NUMERICS (rel_err == 0.0 since R4): per-channel serial fp32 FMA chain
// over the 27 taps in NHWC patch order (kh, kw, c innermost) from 0, bias
// added as a separate fp32 add. Top-k: magnitude strict-> scan, lower index
// wins ties. f32x2 lanes / scalar chains are identical per-lane rn-FMAs.
//
// R15 = R14 with the constant path fixed per SASS_QUICKREF: levels 0-2 read
// __constant__ weights DIRECTLY as uniform scalars (no GPR float4 staging),
// so ptxas can use the uniform-const path (LDCU, floor 1, UR dest, separate
// port) + FFMA-with-UR instead of GPR LDC (floor 8) that sank R14. Level 3
// stays on smem + ffma2. Keys stored as raw float bits (decode free).

#define BT 160
#define OH 254
#define OW 254
#define PLANE (OH * OW)          // 64516
#define NPIX (8 * PLANE)         // 516128
#define NCH 120
#define NPAIR3 32                // level-3 channel pairs (channels 56..119)
#define ENC_BYTES (64 * BT * 4)  // 40960 (dynamic smem)

__constant__ float cw28[NCH * 28];   // padded weights: cw28[c*28 + q], q<27
__constant__ float cbias[NCH];

__device__ __forceinline__ unsigned long long ffma2(unsigned long long a,
                                                    unsigned long long bb_,
                                                    unsigned long long c) {
    unsigned long long d;
    asm("fma.rn.f32x2 %0, %1, %2, %3;" : "=l"(d) : "l"(a), "l"(bb_), "l"(c));
    return d;
}
__device__ __forceinline__ unsigned long long pack2(float lo, float hi) {
    unsigned long long r;
    asm("mov.b64 %0, {%1, %2};" : "=l"(r) : "f"(lo), "f"(hi));
    return r;
}
__device__ __forceinline__ void unpack2(unsigned long long v, float& lo, float& hi) {
    asm("mov.b64 {%0, %1}, %2;" : "=f"(lo), "=f"(hi) : "l"(v));
}
__device__ __forceinline__ float lo2(unsigned long long v) {
    float a, b2;
    unpack2(v, a, b2);
    return a;          // register alias of the low half (no data movement)
}

// Gating: selected j -> enable bits 2j..2j+3 (mod 2n). Branch-free bit-spread.
// Validated rel_err==0.0 in R8-R14. Handles the j==31 wrap for n=32.
__device__ __forceinline__ unsigned long long gate_from_sel(unsigned m, int n) {
    unsigned long long xv = m;
    xv = (xv | (xv << 16)) & 0x0000FFFF0000FFFFull;
    xv = (xv | (xv << 8 )) & 0x00FF00FF00FF00FFull;
    xv = (xv | (xv << 4 )) & 0x0F0F0F0F0F0F0F0Full;
    xv = (xv | (xv << 2 )) & 0x3333333333333333ull;
    xv = (xv | (xv << 1 )) & 0x5555555555555555ull;     // bit j -> bit 2j
    unsigned long long gg = xv | (xv << 1) | (xv << 2) | (xv << 3);
    if (n == 32 && (m >> 31)) gg |= 0x3ull;             // wrap of j=31
    const int Wn = n * 2;
    if (Wn < 64)
        gg = (gg | (gg >> Wn)) & ((1ull << Wn) - 1ull);
    return gg;
}

__global__ void __launch_bounds__(BT, 4)
hrtk_kernel(const float* __restrict__ x,
            const float* __restrict__ w,
            const float* __restrict__ b,
            float* __restrict__ out)
{
    // Level-3-only pair-interleaved weights (pairs 28..59):
    // wsh2[lp*56 + 2q+e] = w[56 + 2lp + e][q]; +54/+55 = biases.
    __shared__ float wsh2[NPAIR3 * 56];              // 7168 B (static)
    extern __shared__ unsigned sEnc[];               // 64 key columns x BT (dynamic)

    const int t = threadIdx.x;

    for (int q = t; q < NPAIR3 * 56; q += BT) {
        const int lp = q / 56;
        const int r  = q - lp * 56;
        wsh2[q] = (r < 54) ? w[(56 + lp * 2 + (r & 1)) * 27 + (r >> 1)]
                           : b[56 + lp * 2 + (r - 54)];
    }
    __syncthreads();

    const int p = blockIdx.x * BT + t;
    if (p >= NPIX) return;
    // NPIX = 160*3225 + 128: tail block keeps warps 0-3 fully live, warp 4
    // exits whole -> full-mask shuffles safe in every surviving warp.

    const int ww = p % OW;
    const int rest = p / OW;
    const int hh = rest % OH;
    const int bb = rest / OH;

    unsigned long long win2[27];
    const float* xb = x + (size_t)bb * (3 * 65536) + hh * 256 + ww;
#pragma unroll
    for (int ci = 0; ci < 3; ci++)
#pragma unroll
        for (int kh = 0; kh < 3; kh++)
#pragma unroll
            for (int kw = 0; kw < 3; kw++) {
                const float v = __ldg(xb + ci * 65536 + kh * 256 + kw);
                win2[ci * 9 + kh * 3 + kw] = pack2(v, v);
            }

    float* ob = out + (size_t)bb * (NCH * PLANE) + hh * OW + ww;

    unsigned long long gate = ~0ull;
    int base = 0;

#pragma unroll
    for (int lvl = 0; lvl < 4; lvl++) {
        const int n = 8 << lvl;   // 8,16,32,64
        const int k = 2 << lvl;   // 2,4,8,16
        const int G = n >> 3;     // groups of 8 channels

        // Warp-union of gates (uniform liveness for dead-group skip).
        unsigned long long ugate = ~0ull;
        if (lvl > 0) {
            unsigned lo = (unsigned)gate, hi = (unsigned)(gate >> 32);
#pragma unroll
            for (int o = 16; o; o >>= 1) {
                lo |= __shfl_xor_sync(0xffffffffu, lo, o);
                hi |= __shfl_xor_sync(0xffffffffu, hi, o);
            }
            ugate = ((unsigned long long)hi << 32) | lo;
        }

        unsigned gmag[8];
#pragma unroll
        for (int g = 0; g < 8; g++) gmag[g] = 0u;

        // ---- conv + encode + zero-prefill + group-max build ----
#pragma unroll
        for (int g = 0; g < G; g++) {
            const int ib = g << 3;
            unsigned gm = 0u;
            if (((ugate >> ib) & 0xFFull) == 0ull) {
#pragma unroll
                for (int j = 0; j < 8; j++) {
                    sEnc[(ib + j) * BT + t] = 0u;
                    ob[(base + ib + j) * PLANE] = 0.0f;
                }
            } else {
#pragma unroll
                for (int j2 = 0; j2 < 4; j2++) {            // 4 channel-pairs
                    const int i0 = ib + j2 * 2;
                    float act0, act1;

                    if (lvl < 3) {
                        // Uniform-const path: direct scalar refs, uniform index
                        // -> LDCU (floor 1, UR dest) + FFMA-with-UR. Two
                        // interleaved chains, frozen per-lane Eigen order.
                        const int c0 = base + i0;
                        const float* w0 = cw28 + c0 * 28;
                        const float* w1 = w0 + 28;
                        float a0 = 0.0f, a1 = 0.0f;
#pragma unroll
                        for (int kh = 0; kh < 3; kh++)
#pragma unroll
                            for (int kw = 0; kw < 3; kw++)
#pragma unroll
                                for (int ci = 0; ci < 3; ci++) {
                                    const int q = ci * 9 + kh * 3 + kw;
                                    const float wv = lo2(win2[q]);
                                    a0 = fmaf(wv, w0[q], a0);
                                    a1 = fmaf(wv, w1[q], a1);
                                }
                        act0 = a0 + cbias[c0];
                        act1 = a1 + cbias[c0 + 1];
                    } else {
                        // Smem path (level 3): pair-interleaved ffma2 chain.
                        const int lp = (base + i0 - 56) >> 1;
                        const float4* wv = (const float4*)(wsh2 + lp * 56);
                        float wrp[56];
#pragma unroll
                        for (int z = 0; z < 14; z++) *(float4*)&wrp[4 * z] = wv[z];

                        unsigned long long acc = 0ull;
#pragma unroll
                        for (int kh = 0; kh < 3; kh++)
#pragma unroll
                            for (int kw = 0; kw < 3; kw++)
#pragma unroll
                                for (int ci = 0; ci < 3; ci++) {
                                    const int q = ci * 9 + kh * 3 + kw;
                                    acc = ffma2(win2[q],
                                                *(const unsigned long long*)&wrp[2 * q],
                                                acc);
                                }
                        float a0, a1;
                        unpack2(acc, a0, a1);
                        act0 = a0 + wrp[54];
                        act1 = a1 + wrp[55];
                    }

                    // Raw-bits keys: mag = bits & 0x7FFFFFFF, decode is identity.
                    unsigned k0 = __float_as_uint(act0);
                    unsigned k1 = __float_as_uint(act1);
                    k0 = ((unsigned)(gate >> (i0    )) & 1u) ? k0 : 0u;
                    k1 = ((unsigned)(gate >> (i0 + 1)) & 1u) ? k1 : 0u;
                    sEnc[(i0    ) * BT + t] = k0;
                    sEnc[(i0 + 1) * BT + t] = k1;
                    ob[(base + i0    ) * PLANE] = 0.0f;
                    ob[(base + i0 + 1) * PLANE] = 0.0f;
                    const unsigned um0 = k0 & 0x7FFFFFFFu;
                    const unsigned um1 = k1 & 0x7FFFFFFFu;
                    if (um0 > gm) gm = um0;                  // ascending order:
                    if (um1 > gm) gm = um1;                  // first-wins kept
                }
            }
            gmag[g] = gm;
        }

        // ---- k extractions: register group-max scan + one 8-slot rescan ----
        unsigned selmask = 0u;
#pragma unroll 1
        for (int s = 0; s < k; s++) {
            unsigned bm = 0u;
            int bg = 0;
#pragma unroll
            for (int g = 0; g < 8; g++)
                if (g < G && gmag[g] > bm) { bm = gmag[g]; bg = g; }  // strict >
            if (!bm) break;                       // all remaining keys are zero

            unsigned m2 = 0u, ufull = 0u, found = 0u;
            int leaf = 0;
            const int gb = bg << 3;
#pragma unroll
            for (int j = 0; j < 8; j++) {
                const unsigned u = sEnc[(gb + j) * BT + t];
                const unsigned um = u & 0x7FFFFFFFu;
                if (um == bm && !found) { found = 1u; leaf = j; ufull = u; }
                else if (um > m2) m2 = um;
            }
            const int mi = gb + leaf;
            ob[(base + mi) * PLANE] = __uint_as_float(ufull);
            sEnc[mi * BT + t] = 0u;
#pragma unroll
            for (int g = 0; g < 8; g++)
                if (g == bg) gmag[g] = m2;
            selmask |= 1u << mi;
        }

        if (lvl < 3)
            gate = gate_from_sel(selmask, n);
        base += n;
    }
}

extern "C" void kernel_launch(void* const* d_in, const int* in_sizes, int n_in,
                              void* d_out, int out_size)
{
    const float* x = (const float*)d_in[0];
    const float* w = (const float*)d_in[1];
    const float* b = (const float*)d_in[2];
    float* out = (float*)d_out;

    static void* cw_addr = nullptr;
    if (!cw_addr) {
        cudaFuncSetAttribute(hrtk_kernel,
                             cudaFuncAttributeMaxDynamicSharedMemorySize,
                             ENC_BYTES);
        cudaGetSymbolAddress(&cw_addr, cw28);
    }

    // Re-layout OIHW (27f/ch) -> padded (28f/ch) constant in one memcpy node.
    cudaMemcpy2DAsync(cw_addr, 28 * sizeof(float),
                      w, 27 * sizeof(float),
                      27 * sizeof(float), NCH,
                      cudaMemcpyDeviceToDevice);
    cudaMemcpyToSymbolAsync(cbias, b, NCH * sizeof(float), 0,
                            cudaMemcpyDeviceToDevice);

    const int grid = (NPIX + BT - 1) / BT;
    hrtk_kernel<<<grid, BT, ENC_BYTES>>>(x, w, b, out);
}

// round 17
// speedup vs baseline: 1.0699x; 1.0179x over previous
#include <cuda_runtime.h>
#include <stdint.h>

// HierarchicalRingTopK: 3x3x3 VALID conv (120 ch) + 4-level gated top-k keep.
// x: (8,3,256,256) f32, w: (120,3,3,3) f32, b: (120,) f32 -> out: (8,120,254,254) f32
//
// FROZEN NUMERICS (rel_err == 0.0 since R4): per-channel serial fp32 FMA chain
// over the 27 taps in NHWC patch order (kh, kw, c innermost) from 0, bias
// added as a separate fp32 add. Keys = raw float bits (mag = bits&0x7FFFFFFF).
// Top-k: magnitude strict-> scan, lower index wins ties. f32x2 lanes are
// independent rn-FMAs (bit-identical).
//
// R16 = R11 body (best measured per-warp dataflow: BT=160, pair-interleaved
// smem weights + ffma2, dynamic sEnc, 20 warps/SM) wrapped in a PERSISTENT
// grid of 592 CTAs (exactly one wave) with atomic work-stealing over the
// 3226 pixel tiles. Removes the 5.45-wave quantization tail (~8-9% of dur).
// Tile outputs are pure per-pixel -> deterministic regardless of assignment.

#define BT 160
#define OH 254
#define OW 254
#define PLANE (OH * OW)          // 64516
#define NPIX (8 * PLANE)         // 516128
#define NTILES ((NPIX + BT - 1) / BT)   // 3226
#define NBLK (148 * 4)           // 592 persistent CTAs = one full wave
#define NCH 120
#define NPAIR (NCH / 2)          // 60
#define ENC_BYTES (64 * BT * 4)  // 40960 (dynamic smem)

__device__ int g_tile_ctr;       // next unclaimed tile (reset to NBLK each launch)

__global__ void reset_ctr_kernel() { g_tile_ctr = NBLK; }

__device__ __forceinline__ unsigned long long ffma2(unsigned long long a,
                                                    unsigned long long bb_,
                                                    unsigned long long c) {
    unsigned long long d;
    asm("fma.rn.f32x2 %0, %1, %2, %3;" : "=l"(d) : "l"(a), "l"(bb_), "l"(c));
    return d;
}
__device__ __forceinline__ unsigned long long pack2(float lo, float hi) {
    unsigned long long r;
    asm("mov.b64 %0, {%1, %2};" : "=l"(r) : "f"(lo), "f"(hi));
    return r;
}
__device__ __forceinline__ void unpack2(unsigned long long v, float& lo, float& hi) {
    asm("mov.b64 {%0, %1}, %2;" : "=f"(lo), "=f"(hi) : "l"(v));
}

// Gating: selected j -> enable bits 2j..2j+3 (mod 2n). Branch-free bit-spread.
// Validated rel_err==0.0 in R8-R15. Handles the j==31 wrap for n=32.
__device__ __forceinline__ unsigned long long gate_from_sel(unsigned m, int n) {
    unsigned long long xv = m;
    xv = (xv | (xv << 16)) & 0x0000FFFF0000FFFFull;
    xv = (xv | (xv << 8 )) & 0x00FF00FF00FF00FFull;
    xv = (xv | (xv << 4 )) & 0x0F0F0F0F0F0F0F0Full;
    xv = (xv | (xv << 2 )) & 0x3333333333333333ull;
    xv = (xv | (xv << 1 )) & 0x5555555555555555ull;     // bit j -> bit 2j
    unsigned long long gg = xv | (xv << 1) | (xv << 2) | (xv << 3);
    if (n == 32 && (m >> 31)) gg |= 0x3ull;             // wrap of j=31
    const int Wn = n * 2;
    if (Wn < 64)
        gg = (gg | (gg >> Wn)) & ((1ull << Wn) - 1ull);
    return gg;
}

__global__ void __launch_bounds__(BT, 4)
hrtk_kernel(const float* __restrict__ x,
            const float* __restrict__ w,
            const float* __restrict__ b,
            float* __restrict__ out)
{
    // Pair-interleaved weights: wsh2[pr*56 + 2q+e] = w[2pr+e][q]; +54/+55 = biases.
    __shared__ float wsh2[NPAIR * 56];               // 13440 B (static)
    __shared__ int   tileS;
    extern __shared__ unsigned sEnc[];               // 64 key columns x BT (dynamic)

    const int t = threadIdx.x;

    for (int q = t; q < NPAIR * 56; q += BT) {
        const int pr = q / 56;
        const int r  = q - pr * 56;
        wsh2[q] = (r < 54) ? w[(pr * 2 + (r & 1)) * 27 + (r >> 1)]
                           : b[pr * 2 + (r - 54)];
    }
    __syncthreads();

    int tile = blockIdx.x;

    for (;;) {
        if (tile >= NTILES) break;                   // uniform within CTA

        const int p = tile * BT + t;
        if (p < NPIX) {
            // Tail tile (3225) keeps warps 0-3 fully live; warp 4 skips whole
            // -> full-mask shuffles safe in every executing warp.
            const int ww = p % OW;
            const int rest = p / OW;
            const int hh = rest % OH;
            const int bb = rest / OH;

            unsigned long long win2[27];
            const float* xb = x + (size_t)bb * (3 * 65536) + hh * 256 + ww;
#pragma unroll
            for (int ci = 0; ci < 3; ci++)
#pragma unroll
                for (int kh = 0; kh < 3; kh++)
#pragma unroll
                    for (int kw = 0; kw < 3; kw++) {
                        const float v = __ldg(xb + ci * 65536 + kh * 256 + kw);
                        win2[ci * 9 + kh * 3 + kw] = pack2(v, v);
                    }

            float* ob = out + (size_t)bb * (NCH * PLANE) + hh * OW + ww;

            unsigned long long gate = ~0ull;
            int base = 0;

#pragma unroll
            for (int lvl = 0; lvl < 4; lvl++) {
                const int n = 8 << lvl;   // 8,16,32,64
                const int k = 2 << lvl;   // 2,4,8,16
                const int G = n >> 3;     // groups of 8 channels

                // Warp-union of gates (uniform liveness for dead-group skip).
                unsigned long long ugate = ~0ull;
                if (lvl > 0) {
                    unsigned lo = (unsigned)gate, hi = (unsigned)(gate >> 32);
#pragma unroll
                    for (int o = 16; o; o >>= 1) {
                        lo |= __shfl_xor_sync(0xffffffffu, lo, o);
                        hi |= __shfl_xor_sync(0xffffffffu, hi, o);
                    }
                    ugate = ((unsigned long long)hi << 32) | lo;
                }

                unsigned gmag[8];
#pragma unroll
                for (int g = 0; g < 8; g++) gmag[g] = 0u;

                // ---- conv + encode + zero-prefill + group-max build ----
#pragma unroll
                for (int g = 0; g < G; g++) {
                    const int ib = g << 3;
                    unsigned gm = 0u;
                    if (((ugate >> ib) & 0xFFull) == 0ull) {
#pragma unroll
                        for (int j = 0; j < 8; j++) {
                            sEnc[(ib + j) * BT + t] = 0u;
                            ob[(base + ib + j) * PLANE] = 0.0f;
                        }
                    } else {
#pragma unroll
                        for (int j2 = 0; j2 < 4; j2++) {     // 4 channel-pairs
                            const int i0 = ib + j2 * 2;
                            const int pr = (base + i0) >> 1;
                            const float4* wv = (const float4*)(wsh2 + pr * 56);
                            float wrp[56];
#pragma unroll
                            for (int z = 0; z < 14; z++)
                                *(float4*)&wrp[4 * z] = wv[z];

                            // FROZEN: Eigen/NHWC tap order, per-lane serial chain.
                            unsigned long long acc = 0ull;
#pragma unroll
                            for (int kh = 0; kh < 3; kh++)
#pragma unroll
                                for (int kw = 0; kw < 3; kw++)
#pragma unroll
                                    for (int ci = 0; ci < 3; ci++) {
                                        const int q = ci * 9 + kh * 3 + kw;
                                        acc = ffma2(win2[q],
                                                    *(const unsigned long long*)&wrp[2 * q],
                                                    acc);
                                    }
                            float a0, a1;
                            unpack2(acc, a0, a1);
                            const float act0 = a0 + wrp[54];
                            const float act1 = a1 + wrp[55];

                            // Raw-bits keys (decode is identity).
                            unsigned k0 = __float_as_uint(act0);
                            unsigned k1 = __float_as_uint(act1);
                            k0 = ((unsigned)(gate >> (i0    )) & 1u) ? k0 : 0u;
                            k1 = ((unsigned)(gate >> (i0 + 1)) & 1u) ? k1 : 0u;
                            sEnc[(i0    ) * BT + t] = k0;
                            sEnc[(i0 + 1) * BT + t] = k1;
                            ob[(base + i0    ) * PLANE] = 0.0f;
                            ob[(base + i0 + 1) * PLANE] = 0.0f;
                            const unsigned um0 = k0 & 0x7FFFFFFFu;
                            const unsigned um1 = k1 & 0x7FFFFFFFu;
                            if (um0 > gm) gm = um0;          // ascending order:
                            if (um1 > gm) gm = um1;          // first-wins kept
                        }
                    }
                    gmag[g] = gm;
                }

                // ---- k extractions: register group-max + one 8-slot rescan ----
                unsigned selmask = 0u;
#pragma unroll 1
                for (int s = 0; s < k; s++) {
                    unsigned bm = 0u;
                    int bg = 0;
#pragma unroll
                    for (int g = 0; g < 8; g++)
                        if (g < G && gmag[g] > bm) { bm = gmag[g]; bg = g; }
                    if (!bm) break;           // all remaining keys are zero

                    unsigned m2 = 0u, ufull = 0u, found = 0u;
                    int leaf = 0;
                    const int gb = bg << 3;
#pragma unroll
                    for (int j = 0; j < 8; j++) {
                        const unsigned u = sEnc[(gb + j) * BT + t];
                        const unsigned um = u & 0x7FFFFFFFu;
                        if (um == bm && !found) { found = 1u; leaf = j; ufull = u; }
                        else if (um > m2) m2 = um;
                    }
                    const int mi = gb + leaf;
                    ob[(base + mi) * PLANE] = __uint_as_float(ufull);
                    sEnc[mi * BT + t] = 0u;
#pragma unroll
                    for (int g = 0; g < 8; g++)
                        if (g == bg) gmag[g] = m2;
                    selmask |= 1u << mi;
                }

                if (lvl < 3)
                    gate = gate_from_sel(selmask, n);
                base += n;
            }
        }

        // ---- grab next tile (dynamic work-stealing; body has no BARs) ----
        __syncthreads();                      // all done reading prior tileS
        if (t == 0) tileS = atomicAdd(&g_tile_ctr, 1);
        __syncthreads();
        tile = tileS;
    }
}

extern "C" void kernel_launch(void* const* d_in, const int* in_sizes, int n_in,
                              void* d_out, int out_size)
{
    const float* x = (const float*)d_in[0];
    const float* w = (const float*)d_in[1];
    const float* b = (const float*)d_in[2];
    float* out = (float*)d_out;

    static int smem_ok = 0;
    if (!smem_ok) {
        cudaFuncSetAttribute(hrtk_kernel,
                             cudaFuncAttributeMaxDynamicSharedMemorySize,
                             ENC_BYTES);
        smem_ok = 1;
    }

    reset_ctr_kernel<<<1, 1>>>();
    hrtk_kernel<<<NBLK, BT, ENC_BYTES>>>(x, w, b, out);
}